// round 14
// baseline (speedup 1.0000x reference)
#include <cuda_runtime.h>
#include <cuda_bf16.h>
#include <math.h>
#include <stdint.h>

// Problem constants
#define B_SZ    4096
#define N_IN    7
#define PC_DIM  256
#define K_CAPS  25
#define MC_DIM  128
#define KM      (K_CAPS * MC_DIM)      // 3200
#define VOTES_PER_B (N_IN * KM)        // 22400
#define POSE_STRIDE (N_IN * PC_DIM)    // 1792
#define LN_EPS  1e-5f
#define AGREE_SCALE 0.08838834764831845f   // 1/sqrt(128)
#define NFIELD  84                     // 28 Q + 28 Gg + 7 T + 7 Sg + 7 Bv + 7 Wc

// scratch
__device__ float g_votes[(size_t)B_SZ * VOTES_PER_B];                 // 367 MB fp32
__device__ float g_sum[(size_t)B_SZ * NFIELD * K_CAPS];               // 34.4 MB
__device__ __nv_bfloat16 g_pa_hi[(size_t)B_SZ * POSE_STRIDE];
__device__ __nv_bfloat16 g_pa_lo[(size_t)B_SZ * POSE_STRIDE];
__device__ __nv_bfloat16 g_wt_hi[(size_t)N_IN * KM * PC_DIM];
__device__ __nv_bfloat16 g_wt_lo[(size_t)N_IN * KM * PC_DIM];

// ---------------- helpers ----------------
__device__ __forceinline__ void mma_bf16(float& c0, float& c1, float& c2, float& c3,
                                         unsigned a0, unsigned a1, unsigned a2, unsigned a3,
                                         unsigned b0, unsigned b1) {
    asm volatile(
        "mma.sync.aligned.m16n8k16.row.col.f32.bf16.bf16.f32 "
        "{%0,%1,%2,%3}, {%4,%5,%6,%7}, {%8,%9}, {%0,%1,%2,%3};\n"
        : "+f"(c0), "+f"(c1), "+f"(c2), "+f"(c3)
        : "r"(a0), "r"(a1), "r"(a2), "r"(a3), "r"(b0), "r"(b1));
}
__device__ __forceinline__ void ldmatrix_x4(unsigned& r0, unsigned& r1,
                                            unsigned& r2, unsigned& r3, uint32_t addr) {
    asm volatile("ldmatrix.sync.aligned.m8n8.x4.shared.b16 {%0,%1,%2,%3}, [%4];"
                 : "=r"(r0), "=r"(r1), "=r"(r2), "=r"(r3) : "r"(addr));
}
__device__ __forceinline__ void cp_async16(uint32_t dst, const void* src) {
    asm volatile("cp.async.cg.shared.global [%0], [%1], 16;\n" :: "r"(dst), "l"(src));
}
__device__ __forceinline__ void cp_commit() { asm volatile("cp.async.commit_group;\n"); }
__device__ __forceinline__ void cp_wait0() { asm volatile("cp.async.wait_group 0;\n" ::: "memory"); }
__device__ __forceinline__ void cp_wait1() { asm volatile("cp.async.wait_group 1;\n" ::: "memory"); }
__device__ __forceinline__ void cp_wait3() { asm volatile("cp.async.wait_group 3;\n" ::: "memory"); }

__device__ __forceinline__ float warp_sum(float v) {
    #pragma unroll
    for (int o = 16; o; o >>= 1) v += __shfl_xor_sync(0xffffffffu, v, o);
    return v;
}
__device__ __forceinline__ float warp_max(float v) {
    #pragma unroll
    for (int o = 16; o; o >>= 1) v = fmaxf(v, __shfl_xor_sync(0xffffffffu, v, o));
    return v;
}
__device__ __forceinline__ uint32_t smem_u32(const void* p) {
    return (uint32_t)__cvta_generic_to_shared(p);
}
__device__ __forceinline__ float dot4(const float4 a, const float4 b) {
    return fmaf(a.x, b.x, fmaf(a.y, b.y, fmaf(a.z, b.z, a.w * b.w)));
}
__device__ __forceinline__ float sum4(const float4 a) {
    return (a.x + a.y) + (a.z + a.w);
}

// ---------------------------------------------------------------------------
// Fused decompose kernel (poses + w-transpose in one grid). (R11-exact)
// ---------------------------------------------------------------------------
#define PO_N2    (B_SZ * POSE_STRIDE / 2)
#define PO_BLKS  ((PO_N2 + 255) / 256)
#define WT_BLKS  ((KM / 32) * (PC_DIM / 32) * N_IN)

__global__ __launch_bounds__(256) void decomp_fused_kernel(
    const float* __restrict__ poses, const float* __restrict__ w,
    __nv_bfloat16* __restrict__ pa_hi, __nv_bfloat16* __restrict__ pa_lo,
    __nv_bfloat16* __restrict__ wt_hi, __nv_bfloat16* __restrict__ wt_lo)
{
    const int tid = threadIdx.x;
    if (blockIdx.x < PO_BLKS) {
        const int i = blockIdx.x * 256 + tid;
        if (i >= PO_N2) return;
        const float2 x = ((const float2*)poses)[i];
        const __nv_bfloat16 h0 = __float2bfloat16(x.x);
        const __nv_bfloat16 h1 = __float2bfloat16(x.y);
        const __nv_bfloat16 l0 = __float2bfloat16(x.x - __bfloat162float(h0));
        const __nv_bfloat16 l1 = __float2bfloat16(x.y - __bfloat162float(h1));
        ((__nv_bfloat162*)pa_hi)[i] = __nv_bfloat162(h0, h1);
        ((__nv_bfloat162*)pa_lo)[i] = __nv_bfloat162(l0, l1);
    } else {
        __shared__ float tile[32][33];
        const int bid = blockIdx.x - PO_BLKS;
        const int km0 = (bid % (KM / 32)) * 32;
        const int d0  = ((bid / (KM / 32)) % (PC_DIM / 32)) * 32;
        const int n   = bid / ((KM / 32) * (PC_DIM / 32));
        const int tx = tid & 31, ty = tid >> 5;
        #pragma unroll
        for (int j = 0; j < 4; j++) {
            const int d = d0 + ty + 8 * j;
            tile[ty + 8 * j][tx] = w[((size_t)n * PC_DIM + d) * KM + km0 + tx];
        }
        __syncthreads();
        #pragma unroll
        for (int j = 0; j < 4; j++) {
            const int km = km0 + ty + 8 * j;
            const float x = tile[tx][ty + 8 * j];
            const __nv_bfloat16 h = __float2bfloat16(x);
            const __nv_bfloat16 l = __float2bfloat16(x - __bfloat162float(h));
            const size_t o = ((size_t)n * KM + km) * PC_DIM + d0 + tx;
            wt_hi[o] = h;
            wt_lo[o] = l;
        }
    }
}

// ---------------------------------------------------------------------------
// Kernel A (R11-exact): bf16 3-term split GEMM, mma.sync + ldmatrix,
// kc-major tile reuse. grid (25, 32, 7), 256 threads, 2 CTAs/SM.
// ---------------------------------------------------------------------------
#define PITCH 72
#define TILE_BYTES (128 * PITCH * 2)
#define VOTES_SMEM (6 * TILE_BYTES)

__global__ __launch_bounds__(256, 2) void votes_hmma_kernel(
    const __nv_bfloat16* __restrict__ pa_hi,
    const __nv_bfloat16* __restrict__ pa_lo,
    const __nv_bfloat16* __restrict__ wt_hi,
    const __nv_bfloat16* __restrict__ wt_lo)
{
    extern __shared__ __nv_bfloat16 smem[];
    const uint32_t base = smem_u32(smem);
    const uint32_t SLOT_BH = base + 4 * TILE_BYTES;
    const uint32_t SLOT_BL = base + 5 * TILE_BYTES;

    const int tid  = threadIdx.x;
    const int lane = tid & 31;
    const int wrp  = tid >> 5;
    const int wm   = wrp >> 2;
    const int wn   = wrp & 3;

    const int tn = blockIdx.x;
    const int tm = blockIdx.y;
    const int n  = blockIdx.z;

    const int a_off = (((lane & 7) | (((lane >> 3) & 1) << 3)) * PITCH)
                    + ((lane >> 4) << 3) + wm * 64 * PITCH;
    const int b_off = (((lane & 7) | (((lane >> 4) & 1) << 3)) * PITCH)
                    + (((lane >> 3) & 1) << 3) + wn * 32 * PITCH;

    const __nv_bfloat16* Abase_h = pa_hi + (size_t)(tm * 128) * POSE_STRIDE + n * PC_DIM;
    const __nv_bfloat16* Abase_l = pa_lo + (size_t)(tm * 128) * POSE_STRIDE + n * PC_DIM;
    const __nv_bfloat16* Bbase_h = wt_hi + ((size_t)n * KM + tn * 128) * PC_DIM;
    const __nv_bfloat16* Bbase_l = wt_lo + ((size_t)n * KM + tn * 128) * PC_DIM;

    auto load_tile = [&](uint32_t dst, const __nv_bfloat16* src, int stride, int kc) {
        const __nv_bfloat16* s = src + kc * 64;
        #pragma unroll
        for (int i = 0; i < 4; i++) {
            const int idx = tid + 256 * i;
            const int r = idx >> 3, c = idx & 7;
            cp_async16(dst + (uint32_t)(r * PITCH * 2 + c * 16),
                       s + (size_t)r * stride + c * 8);
        }
        cp_commit();
    };

    float acc[4][4][4];
    #pragma unroll
    for (int mi = 0; mi < 4; mi++)
        #pragma unroll
        for (int ni = 0; ni < 4; ni++)
            #pragma unroll
            for (int c = 0; c < 4; c++) acc[mi][ni][c] = 0.f;

    auto pass = [&](uint32_t Aslot, uint32_t Bslot) {
        #pragma unroll
        for (int ks = 0; ks < 4; ks++) {
            unsigned af[4][4];
            #pragma unroll
            for (int mi = 0; mi < 4; mi++)
                ldmatrix_x4(af[mi][0], af[mi][1], af[mi][2], af[mi][3],
                            Aslot + 2u * (uint32_t)(a_off + mi * 16 * PITCH + ks * 16));
            unsigned bf[4][2];
            #pragma unroll
            for (int p = 0; p < 2; p++)
                ldmatrix_x4(bf[2*p][0], bf[2*p][1], bf[2*p+1][0], bf[2*p+1][1],
                            Bslot + 2u * (uint32_t)(b_off + p * 16 * PITCH + ks * 16));
            #pragma unroll
            for (int mi = 0; mi < 4; mi++)
                #pragma unroll
                for (int ni = 0; ni < 4; ni++)
                    mma_bf16(acc[mi][ni][0], acc[mi][ni][1], acc[mi][ni][2], acc[mi][ni][3],
                             af[mi][0], af[mi][1], af[mi][2], af[mi][3],
                             bf[ni][0], bf[ni][1]);
        }
    };

    load_tile(base + 0 * TILE_BYTES, Abase_h, POSE_STRIDE, 0);
    load_tile(base + 2 * TILE_BYTES, Abase_l, POSE_STRIDE, 0);
    load_tile(SLOT_BH, Bbase_h, PC_DIM, 0);
    load_tile(SLOT_BL, Bbase_l, PC_DIM, 0);

    #pragma unroll 1
    for (int kc = 0; kc < 4; ++kc) {
        const uint32_t A_hi = base + (uint32_t)(kc & 1) * TILE_BYTES;
        const uint32_t A_lo = base + (uint32_t)(2 + (kc & 1)) * TILE_BYTES;
        if (kc < 3) {
            load_tile(base + (uint32_t)((kc + 1) & 1) * TILE_BYTES, Abase_h, POSE_STRIDE, kc + 1);
            load_tile(base + (uint32_t)(2 + ((kc + 1) & 1)) * TILE_BYTES, Abase_l, POSE_STRIDE, kc + 1);
        }
        if (kc < 3) cp_wait3(); else cp_wait1();
        __syncthreads();

        pass(A_hi, SLOT_BH);
        pass(A_lo, SLOT_BH);
        __syncthreads();

        if (kc < 3) load_tile(SLOT_BH, Bbase_h, PC_DIM, kc + 1);
        if (kc < 3) cp_wait3(); else cp_wait0();
        __syncthreads();

        pass(A_hi, SLOT_BL);
        __syncthreads();

        if (kc < 3) load_tile(SLOT_BL, Bbase_l, PC_DIM, kc + 1);
    }

    const int grp = lane >> 2, tig = lane & 3;
    #pragma unroll
    for (int mi = 0; mi < 4; mi++) {
        const int row = tm * 128 + wm * 64 + mi * 16 + grp;
        #pragma unroll
        for (int ni = 0; ni < 4; ni++) {
            const int col = tn * 128 + wn * 32 + ni * 8 + 2 * tig;
            float* p0 = g_votes + (size_t)row * VOTES_PER_B + n * KM + col;
            float* p1 = g_votes + (size_t)(row + 8) * VOTES_PER_B + n * KM + col;
            *(float2*)p0 = make_float2(acc[mi][ni][0], acc[mi][ni][1]);
            *(float2*)p1 = make_float2(acc[mi][ni][2], acc[mi][ni][3]);
        }
    }
}

// ---------------------------------------------------------------------------
// Summary kernel: warp per (b,k). Reads votes once, emits 84 fp32 fields:
//  [0..27]  Q[n<=n']  = sum_m v[n]v[n']
//  [28..55] Gg[n<=n'] = sum_m gamma v[n]v[n']
//  [56..62] T[n] = sum_m v[n]      [63..69] Sg[n] = sum_m gamma v[n]
//  [70..76] Bv[n] = sum_m beta v[n][77..83] Wc[n] = sum_m gamma cw v[n]
// layout g_sum[b][f][k] (k contiguous for coalesced routing-lite loads)
// ---------------------------------------------------------------------------
__global__ __launch_bounds__(256) void summary_kernel(
    const float* __restrict__ ln_gamma,
    const float* __restrict__ ln_beta,
    const float* __restrict__ cls_weight)
{
    __shared__ float sf[8][NFIELD];
    const int wid = threadIdx.x >> 5, lane = threadIdx.x & 31;
    const int gw = blockIdx.x * 8 + wid;
    const int b = gw / K_CAPS, k = gw % K_CAPS;

    const float* vb = g_votes + (size_t)b * VOTES_PER_B + k * MC_DIM + lane * 4;
    const float4 g4  = *(const float4*)&ln_gamma[lane * 4];
    const float4 be4 = *(const float4*)&ln_beta[lane * 4];
    const float4 cw4 = *(const float4*)&cls_weight[k * MC_DIM + lane * 4];

    float4 v[N_IN], gv[N_IN];
    #pragma unroll
    for (int n = 0; n < N_IN; n++) {
        v[n] = *(const float4*)(vb + n * KM);
        gv[n] = make_float4(g4.x * v[n].x, g4.y * v[n].y, g4.z * v[n].z, g4.w * v[n].w);
    }

    float* o = sf[wid];
    int idx = 0;
    #pragma unroll
    for (int n = 0; n < N_IN; n++)
        #pragma unroll
        for (int n2 = n; n2 < N_IN; n2++) {
            float s = warp_sum(dot4(v[n], v[n2]));
            if (lane == 0) o[idx] = s;
            idx++;
        }
    #pragma unroll
    for (int n = 0; n < N_IN; n++)
        #pragma unroll
        for (int n2 = n; n2 < N_IN; n2++) {
            float s = warp_sum(dot4(gv[n], v[n2]));
            if (lane == 0) o[idx] = s;
            idx++;
        }
    #pragma unroll
    for (int n = 0; n < N_IN; n++) {
        float s = warp_sum(sum4(v[n]));
        if (lane == 0) o[56 + n] = s;
    }
    #pragma unroll
    for (int n = 0; n < N_IN; n++) {
        float s = warp_sum(sum4(gv[n]));
        if (lane == 0) o[63 + n] = s;
    }
    #pragma unroll
    for (int n = 0; n < N_IN; n++) {
        float s = warp_sum(dot4(be4, v[n]));
        if (lane == 0) o[70 + n] = s;
    }
    #pragma unroll
    for (int n = 0; n < N_IN; n++) {
        float s = warp_sum(dot4(cw4, gv[n]));
        if (lane == 0) o[77 + n] = s;
    }
    __syncwarp();
    #pragma unroll
    for (int j = 0; j < 3; j++) {
        const int f = lane + 32 * j;
        if (f < NFIELD)
            g_sum[((size_t)b * NFIELD + f) * K_CAPS + k] = o[f];
    }
}

// ---------------------------------------------------------------------------
// Routing-lite: warp per b, lane = k. Pure register math, no syncthreads.
// ---------------------------------------------------------------------------
__global__ __launch_bounds__(256) void routing_lite_kernel(
    const float* __restrict__ acts_prior,
    const float* __restrict__ ln_gamma,
    const float* __restrict__ ln_beta,
    const float* __restrict__ cls_weight,
    const float* __restrict__ cls_bias,
    float* __restrict__ out)
{
    const int wid = threadIdx.x >> 5, lane = threadIdx.x & 31;
    const int b = blockIdx.x * 8 + wid;
    const bool act = lane < K_CAPS;
    const int k = act ? lane : 0;

    // per-k constants Uc = sum gamma*cw, Bc = sum beta*cw
    float Uc = 0.f, Bc = 0.f;
    #pragma unroll
    for (int i = 0; i < 32; i++) {
        const float4 g4  = *(const float4*)&ln_gamma[i * 4];
        const float4 be4 = *(const float4*)&ln_beta[i * 4];
        const float4 c4  = *(const float4*)&cls_weight[k * MC_DIM + i * 4];
        Uc += dot4(g4, c4);
        Bc += dot4(be4, c4);
    }

    // load summaries (coalesced: lane = k contiguous)
    const float* S = g_sum + (size_t)b * NFIELD * K_CAPS + k;
    float Q[28], G[28], T[N_IN], Sg[N_IN], Bv[N_IN], Wc[N_IN];
    #pragma unroll
    for (int i = 0; i < 28; i++) Q[i] = S[(size_t)i * K_CAPS];
    #pragma unroll
    for (int i = 0; i < 28; i++) G[i] = S[(size_t)(28 + i) * K_CAPS];
    #pragma unroll
    for (int n = 0; n < N_IN; n++) {
        T[n]  = S[(size_t)(56 + n) * K_CAPS];
        Sg[n] = S[(size_t)(63 + n) * K_CAPS];
        Bv[n] = S[(size_t)(70 + n) * K_CAPS];
        Wc[n] = S[(size_t)(77 + n) * K_CAPS];
    }

    float a[N_IN], ra[N_IN], r[N_IN];
    #pragma unroll
    for (int n = 0; n < N_IN; n++) {
        a[n] = acts_prior[(size_t)b * N_IN + n];
        ra[n] = a[n] * (1.f / 25.f);
        r[n] = 0.f;
    }

    float mu = 0.f, rs = 1.f;
    #pragma unroll
    for (int t = 0; t < 3; t++) {
        // stats of pose_pre = sum ra*v
        mu = 0.f;
        #pragma unroll
        for (int n = 0; n < N_IN; n++) mu = fmaf(ra[n], T[n], mu);
        mu *= (1.f / 128.f);
        float vs = 0.f;
        {
            int idx = 0;
            #pragma unroll
            for (int n = 0; n < N_IN; n++)
                #pragma unroll
                for (int n2 = n; n2 < N_IN; n2++) {
                    const float w = (n == n2) ? 1.f : 2.f;
                    vs = fmaf(w * ra[n] * ra[n2], Q[idx], vs);
                    idx++;
                }
        }
        const float var = vs * (1.f / 128.f) - mu * mu;
        rs = rsqrtf(var + LN_EPS);

        if (t < 2) {
            // u[n] = sum_{n'} ra[n'] * Gg[n,n']
            float u[N_IN];
            #pragma unroll
            for (int n = 0; n < N_IN; n++) u[n] = 0.f;
            {
                int idx = 0;
                #pragma unroll
                for (int n = 0; n < N_IN; n++)
                    #pragma unroll
                    for (int n2 = n; n2 < N_IN; n2++) {
                        u[n] = fmaf(ra[n2], G[idx], u[n]);
                        if (n != n2) u[n2] = fmaf(ra[n], G[idx], u[n2]);
                        idx++;
                    }
            }
            // agree + softmax over k (lanes)
            #pragma unroll
            for (int n = 0; n < N_IN; n++) {
                const float agr = AGREE_SCALE *
                    (rs * (u[n] - mu * Sg[n]) + Bv[n]);
                const float x = act ? agr : -1e30f;
                const float mx = warp_max(x);
                const float e = act ? __expf(x - mx) : 0.f;
                const float ssum = warp_sum(e);
                r[n] = e / ssum;
                ra[n] = r[n] * a[n];
            }
        }
    }

    // logits
    float wsum = 0.f;
    #pragma unroll
    for (int n = 0; n < N_IN; n++) wsum = fmaf(ra[n], Wc[n], wsum);
    const float logit = rs * (wsum - mu * Uc) + Bc + cls_bias[k];

    if (act) {
        out[(size_t)b * K_CAPS + k] = logit;
        #pragma unroll
        for (int n = 0; n < N_IN; n++)
            out[(size_t)B_SZ * K_CAPS + (size_t)b * 175 + n * K_CAPS + k] = r[n];
    }
}

// ---------------------------------------------------------------------------
extern "C" void kernel_launch(void* const* d_in, const int* in_sizes, int n_in,
                              void* d_out, int out_size)
{
    (void)in_sizes; (void)n_in; (void)out_size;
    const float* poses = (const float*)d_in[0];
    const float* acts  = (const float*)d_in[1];
    const float* w     = (const float*)d_in[2];
    const float* gamma = (const float*)d_in[3];
    const float* beta  = (const float*)d_in[4];
    const float* clsw  = (const float*)d_in[5];
    const float* clsb  = (const float*)d_in[6];
    float* out = (float*)d_out;

    __nv_bfloat16 *pa_hi, *pa_lo, *wt_hi, *wt_lo;
    cudaGetSymbolAddress((void**)&pa_hi, g_pa_hi);
    cudaGetSymbolAddress((void**)&pa_lo, g_pa_lo);
    cudaGetSymbolAddress((void**)&wt_hi, g_wt_hi);
    cudaGetSymbolAddress((void**)&wt_lo, g_wt_lo);

    decomp_fused_kernel<<<PO_BLKS + WT_BLKS, 256>>>(poses, w, pa_hi, pa_lo, wt_hi, wt_lo);

    cudaFuncSetAttribute(votes_hmma_kernel,
                         cudaFuncAttributeMaxDynamicSharedMemorySize,
                         VOTES_SMEM);
    votes_hmma_kernel<<<dim3(25, 32, 7), 256, VOTES_SMEM>>>(pa_hi, pa_lo, wt_hi, wt_lo);

    // 4096*25 warps / 8 per CTA
    summary_kernel<<<(B_SZ * K_CAPS) / 8, 256>>>(gamma, beta, clsw);

    // 4096 warps / 8 per CTA
    routing_lite_kernel<<<B_SZ / 8, 256>>>(acts, gamma, beta, clsw, clsb, out);
}

// round 15
// speedup vs baseline: 1.2230x; 1.2230x over previous
#include <cuda_runtime.h>
#include <cuda_bf16.h>
#include <math.h>
#include <stdint.h>

// Problem constants
#define B_SZ    4096
#define N_IN    7
#define PC_DIM  256
#define K_CAPS  25
#define MC_DIM  128
#define KM      (K_CAPS * MC_DIM)      // 3200
#define VOTES_PER_B (N_IN * KM)        // 22400
#define POSE_STRIDE (N_IN * PC_DIM)    // 1792
#define LN_EPS  1e-5f
#define AGREE_SCALE 0.08838834764831845f   // 1/sqrt(128)

// scratch
__device__ float g_votes[(size_t)B_SZ * VOTES_PER_B];                 // 367 MB fp32
__device__ __nv_bfloat16 g_pa_hi[(size_t)B_SZ * POSE_STRIDE];
__device__ __nv_bfloat16 g_pa_lo[(size_t)B_SZ * POSE_STRIDE];
__device__ __nv_bfloat16 g_wt_hi[(size_t)N_IN * KM * PC_DIM];
__device__ __nv_bfloat16 g_wt_lo[(size_t)N_IN * KM * PC_DIM];

// ---------------- helpers ----------------
__device__ __forceinline__ void mma_bf16(float& c0, float& c1, float& c2, float& c3,
                                         unsigned a0, unsigned a1, unsigned a2, unsigned a3,
                                         unsigned b0, unsigned b1) {
    asm volatile(
        "mma.sync.aligned.m16n8k16.row.col.f32.bf16.bf16.f32 "
        "{%0,%1,%2,%3}, {%4,%5,%6,%7}, {%8,%9}, {%0,%1,%2,%3};\n"
        : "+f"(c0), "+f"(c1), "+f"(c2), "+f"(c3)
        : "r"(a0), "r"(a1), "r"(a2), "r"(a3), "r"(b0), "r"(b1));
}
__device__ __forceinline__ void ldmatrix_x4(unsigned& r0, unsigned& r1,
                                            unsigned& r2, unsigned& r3, uint32_t addr) {
    asm volatile("ldmatrix.sync.aligned.m8n8.x4.shared.b16 {%0,%1,%2,%3}, [%4];"
                 : "=r"(r0), "=r"(r1), "=r"(r2), "=r"(r3) : "r"(addr));
}
__device__ __forceinline__ void cp_async16(uint32_t dst, const void* src) {
    asm volatile("cp.async.cg.shared.global [%0], [%1], 16;\n" :: "r"(dst), "l"(src));
}
__device__ __forceinline__ void cp_commit() { asm volatile("cp.async.commit_group;\n"); }
__device__ __forceinline__ void cp_wait0() { asm volatile("cp.async.wait_group 0;\n" ::: "memory"); }
__device__ __forceinline__ void cp_wait1() { asm volatile("cp.async.wait_group 1;\n" ::: "memory"); }
__device__ __forceinline__ void cp_wait3() { asm volatile("cp.async.wait_group 3;\n" ::: "memory"); }

__device__ __forceinline__ float warp_sum(float v) {
    #pragma unroll
    for (int o = 16; o; o >>= 1) v += __shfl_xor_sync(0xffffffffu, v, o);
    return v;
}
__device__ __forceinline__ float warp_max(float v) {
    #pragma unroll
    for (int o = 16; o; o >>= 1) v = fmaxf(v, __shfl_xor_sync(0xffffffffu, v, o));
    return v;
}
__device__ __forceinline__ uint32_t smem_u32(const void* p) {
    return (uint32_t)__cvta_generic_to_shared(p);
}

// ---------------------------------------------------------------------------
// Fused decompose kernel (poses + w-transpose in one grid). (R11-exact)
// ---------------------------------------------------------------------------
#define PO_N2    (B_SZ * POSE_STRIDE / 2)
#define PO_BLKS  ((PO_N2 + 255) / 256)
#define WT_BLKS  ((KM / 32) * (PC_DIM / 32) * N_IN)

__global__ __launch_bounds__(256) void decomp_fused_kernel(
    const float* __restrict__ poses, const float* __restrict__ w,
    __nv_bfloat16* __restrict__ pa_hi, __nv_bfloat16* __restrict__ pa_lo,
    __nv_bfloat16* __restrict__ wt_hi, __nv_bfloat16* __restrict__ wt_lo)
{
    const int tid = threadIdx.x;
    if (blockIdx.x < PO_BLKS) {
        const int i = blockIdx.x * 256 + tid;
        if (i >= PO_N2) return;
        const float2 x = ((const float2*)poses)[i];
        const __nv_bfloat16 h0 = __float2bfloat16(x.x);
        const __nv_bfloat16 h1 = __float2bfloat16(x.y);
        const __nv_bfloat16 l0 = __float2bfloat16(x.x - __bfloat162float(h0));
        const __nv_bfloat16 l1 = __float2bfloat16(x.y - __bfloat162float(h1));
        ((__nv_bfloat162*)pa_hi)[i] = __nv_bfloat162(h0, h1);
        ((__nv_bfloat162*)pa_lo)[i] = __nv_bfloat162(l0, l1);
    } else {
        __shared__ float tile[32][33];
        const int bid = blockIdx.x - PO_BLKS;
        const int km0 = (bid % (KM / 32)) * 32;
        const int d0  = ((bid / (KM / 32)) % (PC_DIM / 32)) * 32;
        const int n   = bid / ((KM / 32) * (PC_DIM / 32));
        const int tx = tid & 31, ty = tid >> 5;
        #pragma unroll
        for (int j = 0; j < 4; j++) {
            const int d = d0 + ty + 8 * j;
            tile[ty + 8 * j][tx] = w[((size_t)n * PC_DIM + d) * KM + km0 + tx];
        }
        __syncthreads();
        #pragma unroll
        for (int j = 0; j < 4; j++) {
            const int km = km0 + ty + 8 * j;
            const float x = tile[tx][ty + 8 * j];
            const __nv_bfloat16 h = __float2bfloat16(x);
            const __nv_bfloat16 l = __float2bfloat16(x - __bfloat162float(h));
            const size_t o = ((size_t)n * KM + km) * PC_DIM + d0 + tx;
            wt_hi[o] = h;
            wt_lo[o] = l;
        }
    }
}

// ---------------------------------------------------------------------------
// Kernel A (R11-exact): bf16 3-term split GEMM, mma.sync + ldmatrix,
// kc-major tile reuse. grid (25, 32, 7), 256 threads, 2 CTAs/SM.
// ---------------------------------------------------------------------------
#define PITCH 72
#define TILE_BYTES (128 * PITCH * 2)
#define VOTES_SMEM (6 * TILE_BYTES)

__global__ __launch_bounds__(256, 2) void votes_hmma_kernel(
    const __nv_bfloat16* __restrict__ pa_hi,
    const __nv_bfloat16* __restrict__ pa_lo,
    const __nv_bfloat16* __restrict__ wt_hi,
    const __nv_bfloat16* __restrict__ wt_lo)
{
    extern __shared__ __nv_bfloat16 smem[];
    const uint32_t base = smem_u32(smem);
    const uint32_t SLOT_BH = base + 4 * TILE_BYTES;
    const uint32_t SLOT_BL = base + 5 * TILE_BYTES;

    const int tid  = threadIdx.x;
    const int lane = tid & 31;
    const int wrp  = tid >> 5;
    const int wm   = wrp >> 2;
    const int wn   = wrp & 3;

    const int tn = blockIdx.x;
    const int tm = blockIdx.y;
    const int n  = blockIdx.z;

    const int a_off = (((lane & 7) | (((lane >> 3) & 1) << 3)) * PITCH)
                    + ((lane >> 4) << 3) + wm * 64 * PITCH;
    const int b_off = (((lane & 7) | (((lane >> 4) & 1) << 3)) * PITCH)
                    + (((lane >> 3) & 1) << 3) + wn * 32 * PITCH;

    const __nv_bfloat16* Abase_h = pa_hi + (size_t)(tm * 128) * POSE_STRIDE + n * PC_DIM;
    const __nv_bfloat16* Abase_l = pa_lo + (size_t)(tm * 128) * POSE_STRIDE + n * PC_DIM;
    const __nv_bfloat16* Bbase_h = wt_hi + ((size_t)n * KM + tn * 128) * PC_DIM;
    const __nv_bfloat16* Bbase_l = wt_lo + ((size_t)n * KM + tn * 128) * PC_DIM;

    auto load_tile = [&](uint32_t dst, const __nv_bfloat16* src, int stride, int kc) {
        const __nv_bfloat16* s = src + kc * 64;
        #pragma unroll
        for (int i = 0; i < 4; i++) {
            const int idx = tid + 256 * i;
            const int r = idx >> 3, c = idx & 7;
            cp_async16(dst + (uint32_t)(r * PITCH * 2 + c * 16),
                       s + (size_t)r * stride + c * 8);
        }
        cp_commit();
    };

    float acc[4][4][4];
    #pragma unroll
    for (int mi = 0; mi < 4; mi++)
        #pragma unroll
        for (int ni = 0; ni < 4; ni++)
            #pragma unroll
            for (int c = 0; c < 4; c++) acc[mi][ni][c] = 0.f;

    auto pass = [&](uint32_t Aslot, uint32_t Bslot) {
        #pragma unroll
        for (int ks = 0; ks < 4; ks++) {
            unsigned af[4][4];
            #pragma unroll
            for (int mi = 0; mi < 4; mi++)
                ldmatrix_x4(af[mi][0], af[mi][1], af[mi][2], af[mi][3],
                            Aslot + 2u * (uint32_t)(a_off + mi * 16 * PITCH + ks * 16));
            unsigned bf[4][2];
            #pragma unroll
            for (int p = 0; p < 2; p++)
                ldmatrix_x4(bf[2*p][0], bf[2*p][1], bf[2*p+1][0], bf[2*p+1][1],
                            Bslot + 2u * (uint32_t)(b_off + p * 16 * PITCH + ks * 16));
            #pragma unroll
            for (int mi = 0; mi < 4; mi++)
                #pragma unroll
                for (int ni = 0; ni < 4; ni++)
                    mma_bf16(acc[mi][ni][0], acc[mi][ni][1], acc[mi][ni][2], acc[mi][ni][3],
                             af[mi][0], af[mi][1], af[mi][2], af[mi][3],
                             bf[ni][0], bf[ni][1]);
        }
    };

    load_tile(base + 0 * TILE_BYTES, Abase_h, POSE_STRIDE, 0);
    load_tile(base + 2 * TILE_BYTES, Abase_l, POSE_STRIDE, 0);
    load_tile(SLOT_BH, Bbase_h, PC_DIM, 0);
    load_tile(SLOT_BL, Bbase_l, PC_DIM, 0);

    #pragma unroll 1
    for (int kc = 0; kc < 4; ++kc) {
        const uint32_t A_hi = base + (uint32_t)(kc & 1) * TILE_BYTES;
        const uint32_t A_lo = base + (uint32_t)(2 + (kc & 1)) * TILE_BYTES;
        if (kc < 3) {
            load_tile(base + (uint32_t)((kc + 1) & 1) * TILE_BYTES, Abase_h, POSE_STRIDE, kc + 1);
            load_tile(base + (uint32_t)(2 + ((kc + 1) & 1)) * TILE_BYTES, Abase_l, POSE_STRIDE, kc + 1);
        }
        if (kc < 3) cp_wait3(); else cp_wait1();
        __syncthreads();

        pass(A_hi, SLOT_BH);
        pass(A_lo, SLOT_BH);
        __syncthreads();

        if (kc < 3) load_tile(SLOT_BH, Bbase_h, PC_DIM, kc + 1);
        if (kc < 3) cp_wait3(); else cp_wait0();
        __syncthreads();

        pass(A_hi, SLOT_BL);
        __syncthreads();

        if (kc < 3) load_tile(SLOT_BL, Bbase_l, PC_DIM, kc + 1);
    }

    const int grp = lane >> 2, tig = lane & 3;
    #pragma unroll
    for (int mi = 0; mi < 4; mi++) {
        const int row = tm * 128 + wm * 64 + mi * 16 + grp;
        #pragma unroll
        for (int ni = 0; ni < 4; ni++) {
            const int col = tn * 128 + wn * 32 + ni * 8 + 2 * tig;
            float* p0 = g_votes + (size_t)row * VOTES_PER_B + n * KM + col;
            float* p1 = g_votes + (size_t)(row + 8) * VOTES_PER_B + n * KM + col;
            *(float2*)p0 = make_float2(acc[mi][ni][0], acc[mi][ni][1]);
            *(float2*)p1 = make_float2(acc[mi][ni][2], acc[mi][ni][3]);
        }
    }
}

// ---------------------------------------------------------------------------
// Kernel B: register-resident routing with software-pipelined vote prefetch.
// 148 CTAs x 800 threads (25 warps). v[] registers are reloaded for sample
// s+1 immediately after their last use in sample s (final aggregate),
// overlapping next-sample DRAM latency with tail LN/logits compute.
// ---------------------------------------------------------------------------
#define RT_GRID 148

__global__ __launch_bounds__(800, 1) void routing_kernel(
    const float* __restrict__ acts_prior,
    const float* __restrict__ ln_gamma,
    const float* __restrict__ ln_beta,
    const float* __restrict__ cls_weight,
    const float* __restrict__ cls_bias,
    float* __restrict__ out)
{
    __shared__ float sa[8];
    __shared__ float sagree[184];
    __shared__ float sra[184];

    const int tid  = threadIdx.x;
    const int wrp  = tid >> 5;
    const int lane = tid & 31;
    const int k    = wrp;

    const float4 g4  = *(const float4*)&ln_gamma[lane * 4];
    const float4 b4  = *(const float4*)&ln_beta[lane * 4];
    const float4 cw4 = *(const float4*)&cls_weight[k * MC_DIM + lane * 4];
    const float  bias = cls_bias[k];

    // prologue: first sample's votes + acts
    float4 v[N_IN];
    {
        const float* vb = g_votes + (size_t)blockIdx.x * VOTES_PER_B
                        + k * MC_DIM + lane * 4;
        #pragma unroll
        for (int n = 0; n < N_IN; n++)
            v[n] = *(const float4*)(vb + n * KM);
    }
    if (tid < N_IN) sa[tid] = acts_prior[(size_t)blockIdx.x * N_IN + tid];
    __syncthreads();

    #pragma unroll 1
    for (int b = blockIdx.x; b < B_SZ; b += RT_GRID) {
        const int bnext = b + RT_GRID;

        float ra[N_IN];
        #pragma unroll
        for (int n = 0; n < N_IN; n++) ra[n] = sa[n] * (1.f / 25.f);

        float4 pose;
        float4 pp;   // pose_pre

        // ---- it 0: aggregate + LN ----
        pp = make_float4(0.f, 0.f, 0.f, 0.f);
        #pragma unroll
        for (int n = 0; n < N_IN; n++) {
            pp.x = fmaf(ra[n], v[n].x, pp.x);
            pp.y = fmaf(ra[n], v[n].y, pp.y);
            pp.z = fmaf(ra[n], v[n].z, pp.z);
            pp.w = fmaf(ra[n], v[n].w, pp.w);
        }
        {
            float s = warp_sum(pp.x + pp.y + pp.z + pp.w);
            const float mu = s * (1.f / 128.f);
            float var = (pp.x - mu) * (pp.x - mu) + (pp.y - mu) * (pp.y - mu)
                      + (pp.z - mu) * (pp.z - mu) + (pp.w - mu) * (pp.w - mu);
            var = warp_sum(var) * (1.f / 128.f);
            const float rs = rsqrtf(var + LN_EPS);
            pose.x = (pp.x - mu) * rs * g4.x + b4.x;
            pose.y = (pp.y - mu) * rs * g4.y + b4.y;
            pose.z = (pp.z - mu) * rs * g4.z + b4.z;
            pose.w = (pp.w - mu) * rs * g4.w + b4.w;
        }

        // ---- it 1, it 2 ----
        #pragma unroll 1
        for (int it = 1; it < 3; ++it) {
            // agree
            #pragma unroll
            for (int n = 0; n < N_IN; n++) {
                float d = v[n].x * pose.x + v[n].y * pose.y
                        + v[n].z * pose.z + v[n].w * pose.w;
                d = warp_sum(d);
                if (lane == 0) sagree[n * K_CAPS + k] = d * AGREE_SCALE;
            }
            __syncthreads();
            // softmax over k per n (warps 0..6)
            if (wrp < N_IN) {
                const float x = (lane < K_CAPS) ? sagree[wrp * K_CAPS + lane] : -1e30f;
                const float mx = warp_max(x);
                const float e = (lane < K_CAPS) ? __expf(x - mx) : 0.f;
                const float ssum = warp_sum(e);
                if (lane < K_CAPS) {
                    const float r = e / ssum;
                    sra[wrp * K_CAPS + lane] = r * sa[wrp];
                    if (it == 2)
                        out[(size_t)B_SZ * K_CAPS + (size_t)b * 175
                            + wrp * K_CAPS + lane] = r;
                }
            }
            __syncthreads();
            #pragma unroll
            for (int n = 0; n < N_IN; n++) ra[n] = sra[n * K_CAPS + k];

            // aggregate
            pp = make_float4(0.f, 0.f, 0.f, 0.f);
            #pragma unroll
            for (int n = 0; n < N_IN; n++) {
                pp.x = fmaf(ra[n], v[n].x, pp.x);
                pp.y = fmaf(ra[n], v[n].y, pp.y);
                pp.z = fmaf(ra[n], v[n].z, pp.z);
                pp.w = fmaf(ra[n], v[n].w, pp.w);
            }

            if (it == 2) break;   // final LN done after prefetch issue

            // LN (it 1)
            {
                float s = warp_sum(pp.x + pp.y + pp.z + pp.w);
                const float mu = s * (1.f / 128.f);
                float var = (pp.x - mu) * (pp.x - mu) + (pp.y - mu) * (pp.y - mu)
                          + (pp.z - mu) * (pp.z - mu) + (pp.w - mu) * (pp.w - mu);
                var = warp_sum(var) * (1.f / 128.f);
                const float rs = rsqrtf(var + LN_EPS);
                pose.x = (pp.x - mu) * rs * g4.x + b4.x;
                pose.y = (pp.y - mu) * rs * g4.y + b4.y;
                pose.z = (pp.z - mu) * rs * g4.z + b4.z;
                pose.w = (pp.w - mu) * rs * g4.w + b4.w;
            }
        }

        // ---- v is dead: issue next sample's loads NOW (overlap with tail) ----
        float anext = 0.f;
        if (bnext < B_SZ) {
            const float* vb = g_votes + (size_t)bnext * VOTES_PER_B
                            + k * MC_DIM + lane * 4;
            #pragma unroll
            for (int n = 0; n < N_IN; n++)
                v[n] = *(const float4*)(vb + n * KM);
            if (tid < N_IN) anext = acts_prior[(size_t)bnext * N_IN + tid];
        }

        // ---- final LN + logits ----
        {
            float s = warp_sum(pp.x + pp.y + pp.z + pp.w);
            const float mu = s * (1.f / 128.f);
            float var = (pp.x - mu) * (pp.x - mu) + (pp.y - mu) * (pp.y - mu)
                      + (pp.z - mu) * (pp.z - mu) + (pp.w - mu) * (pp.w - mu);
            var = warp_sum(var) * (1.f / 128.f);
            const float rs = rsqrtf(var + LN_EPS);
            pose.x = (pp.x - mu) * rs * g4.x + b4.x;
            pose.y = (pp.y - mu) * rs * g4.y + b4.y;
            pose.z = (pp.z - mu) * rs * g4.z + b4.z;
            pose.w = (pp.w - mu) * rs * g4.w + b4.w;
        }
        {
            float d = pose.x * cw4.x + pose.y * cw4.y + pose.z * cw4.z + pose.w * cw4.w;
            d = warp_sum(d);
            if (lane == 0) out[(size_t)b * K_CAPS + k] = d + bias;
        }

        // publish next acts; barrier also protects sagree/sra reuse
        if (bnext < B_SZ && tid < N_IN) sa[tid] = anext;
        __syncthreads();
    }
}

// ---------------------------------------------------------------------------
extern "C" void kernel_launch(void* const* d_in, const int* in_sizes, int n_in,
                              void* d_out, int out_size)
{
    (void)in_sizes; (void)n_in; (void)out_size;
    const float* poses = (const float*)d_in[0];
    const float* acts  = (const float*)d_in[1];
    const float* w     = (const float*)d_in[2];
    const float* gamma = (const float*)d_in[3];
    const float* beta  = (const float*)d_in[4];
    const float* clsw  = (const float*)d_in[5];
    const float* clsb  = (const float*)d_in[6];
    float* out = (float*)d_out;

    __nv_bfloat16 *pa_hi, *pa_lo, *wt_hi, *wt_lo;
    cudaGetSymbolAddress((void**)&pa_hi, g_pa_hi);
    cudaGetSymbolAddress((void**)&pa_lo, g_pa_lo);
    cudaGetSymbolAddress((void**)&wt_hi, g_wt_hi);
    cudaGetSymbolAddress((void**)&wt_lo, g_wt_lo);

    decomp_fused_kernel<<<PO_BLKS + WT_BLKS, 256>>>(poses, w, pa_hi, pa_lo, wt_hi, wt_lo);

    cudaFuncSetAttribute(votes_hmma_kernel,
                         cudaFuncAttributeMaxDynamicSharedMemorySize,
                         VOTES_SMEM);
    votes_hmma_kernel<<<dim3(25, 32, 7), 256, VOTES_SMEM>>>(pa_hi, pa_lo, wt_hi, wt_lo);

    routing_kernel<<<RT_GRID, 800>>>(acts, gamma, beta, clsw, clsb, out);
}

// round 16
// speedup vs baseline: 1.2608x; 1.0310x over previous
#include <cuda_runtime.h>
#include <cuda_bf16.h>
#include <math.h>
#include <stdint.h>

// Problem constants
#define B_SZ    4096
#define N_IN    7
#define PC_DIM  256
#define K_CAPS  25
#define MC_DIM  128
#define KM      (K_CAPS * MC_DIM)      // 3200
#define VOTES_PER_B (N_IN * KM)        // 22400
#define POSE_STRIDE (N_IN * PC_DIM)    // 1792
#define LN_EPS  1e-5f
#define AGREE_SCALE 0.08838834764831845f   // 1/sqrt(128)

// scratch
__device__ float g_votes[(size_t)B_SZ * VOTES_PER_B];                 // 367 MB fp32
__device__ __nv_bfloat16 g_pa_hi[(size_t)B_SZ * POSE_STRIDE];
__device__ __nv_bfloat16 g_pa_lo[(size_t)B_SZ * POSE_STRIDE];
__device__ __nv_bfloat16 g_wt_hi[(size_t)N_IN * KM * PC_DIM];
__device__ __nv_bfloat16 g_wt_lo[(size_t)N_IN * KM * PC_DIM];

// ---------------- helpers ----------------
__device__ __forceinline__ void mma_bf16(float& c0, float& c1, float& c2, float& c3,
                                         unsigned a0, unsigned a1, unsigned a2, unsigned a3,
                                         unsigned b0, unsigned b1) {
    asm volatile(
        "mma.sync.aligned.m16n8k16.row.col.f32.bf16.bf16.f32 "
        "{%0,%1,%2,%3}, {%4,%5,%6,%7}, {%8,%9}, {%0,%1,%2,%3};\n"
        : "+f"(c0), "+f"(c1), "+f"(c2), "+f"(c3)
        : "r"(a0), "r"(a1), "r"(a2), "r"(a3), "r"(b0), "r"(b1));
}
__device__ __forceinline__ void ldmatrix_x4(unsigned& r0, unsigned& r1,
                                            unsigned& r2, unsigned& r3, uint32_t addr) {
    asm volatile("ldmatrix.sync.aligned.m8n8.x4.shared.b16 {%0,%1,%2,%3}, [%4];"
                 : "=r"(r0), "=r"(r1), "=r"(r2), "=r"(r3) : "r"(addr));
}
__device__ __forceinline__ void cp_async16(uint32_t dst, const void* src) {
    asm volatile("cp.async.cg.shared.global [%0], [%1], 16;\n" :: "r"(dst), "l"(src));
}
__device__ __forceinline__ void cp_commit() { asm volatile("cp.async.commit_group;\n"); }
__device__ __forceinline__ void cp_wait0() { asm volatile("cp.async.wait_group 0;\n" ::: "memory"); }
__device__ __forceinline__ void cp_wait1() { asm volatile("cp.async.wait_group 1;\n" ::: "memory"); }

__device__ __forceinline__ float warp_sum(float v) {
    #pragma unroll
    for (int o = 16; o; o >>= 1) v += __shfl_xor_sync(0xffffffffu, v, o);
    return v;
}
__device__ __forceinline__ float warp_max(float v) {
    #pragma unroll
    for (int o = 16; o; o >>= 1) v = fmaxf(v, __shfl_xor_sync(0xffffffffu, v, o));
    return v;
}
__device__ __forceinline__ uint32_t smem_u32(const void* p) {
    return (uint32_t)__cvta_generic_to_shared(p);
}

// ---------------------------------------------------------------------------
// Fused decompose kernel (poses + w-transpose in one grid). (R11-exact)
// ---------------------------------------------------------------------------
#define PO_N2    (B_SZ * POSE_STRIDE / 2)
#define PO_BLKS  ((PO_N2 + 255) / 256)
#define WT_BLKS  ((KM / 32) * (PC_DIM / 32) * N_IN)

__global__ __launch_bounds__(256) void decomp_fused_kernel(
    const float* __restrict__ poses, const float* __restrict__ w,
    __nv_bfloat16* __restrict__ pa_hi, __nv_bfloat16* __restrict__ pa_lo,
    __nv_bfloat16* __restrict__ wt_hi, __nv_bfloat16* __restrict__ wt_lo)
{
    const int tid = threadIdx.x;
    if (blockIdx.x < PO_BLKS) {
        const int i = blockIdx.x * 256 + tid;
        if (i >= PO_N2) return;
        const float2 x = ((const float2*)poses)[i];
        const __nv_bfloat16 h0 = __float2bfloat16(x.x);
        const __nv_bfloat16 h1 = __float2bfloat16(x.y);
        const __nv_bfloat16 l0 = __float2bfloat16(x.x - __bfloat162float(h0));
        const __nv_bfloat16 l1 = __float2bfloat16(x.y - __bfloat162float(h1));
        ((__nv_bfloat162*)pa_hi)[i] = __nv_bfloat162(h0, h1);
        ((__nv_bfloat162*)pa_lo)[i] = __nv_bfloat162(l0, l1);
    } else {
        __shared__ float tile[32][33];
        const int bid = blockIdx.x - PO_BLKS;
        const int km0 = (bid % (KM / 32)) * 32;
        const int d0  = ((bid / (KM / 32)) % (PC_DIM / 32)) * 32;
        const int n   = bid / ((KM / 32) * (PC_DIM / 32));
        const int tx = tid & 31, ty = tid >> 5;
        #pragma unroll
        for (int j = 0; j < 4; j++) {
            const int d = d0 + ty + 8 * j;
            tile[ty + 8 * j][tx] = w[((size_t)n * PC_DIM + d) * KM + km0 + tx];
        }
        __syncthreads();
        #pragma unroll
        for (int j = 0; j < 4; j++) {
            const int km = km0 + ty + 8 * j;
            const float x = tile[tx][ty + 8 * j];
            const __nv_bfloat16 h = __float2bfloat16(x);
            const __nv_bfloat16 l = __float2bfloat16(x - __bfloat162float(h));
            const size_t o = ((size_t)n * KM + km) * PC_DIM + d0 + tx;
            wt_hi[o] = h;
            wt_lo[o] = l;
        }
    }
}

// ---------------------------------------------------------------------------
// Kernel A: bf16 3-term split GEMM, fused-Ah mainloop.
// Per kc: passAB (Ah shared: Ah*Bh + Ah*Bl per ks), then passAlBh (Al*Bh).
// 3 syncs/kc, FIFO commit groups: [A-pair] at head, [BL], [BH] at tails.
// grid (25, 32, 7), 256 threads, warp grid 2(M)x4(N), 2 CTAs/SM.
// ---------------------------------------------------------------------------
#define PITCH 72
#define TILE_BYTES (128 * PITCH * 2)
#define VOTES_SMEM (6 * TILE_BYTES)

__global__ __launch_bounds__(256, 2) void votes_hmma_kernel(
    const __nv_bfloat16* __restrict__ pa_hi,
    const __nv_bfloat16* __restrict__ pa_lo,
    const __nv_bfloat16* __restrict__ wt_hi,
    const __nv_bfloat16* __restrict__ wt_lo)
{
    extern __shared__ __nv_bfloat16 smem[];
    const uint32_t base = smem_u32(smem);
    // slots: A0,A1 (hi parity), A2,A3 (lo parity), BH, BL
    const uint32_t SLOT_BH = base + 4 * TILE_BYTES;
    const uint32_t SLOT_BL = base + 5 * TILE_BYTES;

    const int tid  = threadIdx.x;
    const int lane = tid & 31;
    const int wrp  = tid >> 5;
    const int wm   = wrp >> 2;
    const int wn   = wrp & 3;

    const int tn = blockIdx.x;
    const int tm = blockIdx.y;
    const int n  = blockIdx.z;

    const int a_off = (((lane & 7) | (((lane >> 3) & 1) << 3)) * PITCH)
                    + ((lane >> 4) << 3) + wm * 64 * PITCH;
    const int b_off = (((lane & 7) | (((lane >> 4) & 1) << 3)) * PITCH)
                    + (((lane >> 3) & 1) << 3) + wn * 32 * PITCH;

    const __nv_bfloat16* Abase_h = pa_hi + (size_t)(tm * 128) * POSE_STRIDE + n * PC_DIM;
    const __nv_bfloat16* Abase_l = pa_lo + (size_t)(tm * 128) * POSE_STRIDE + n * PC_DIM;
    const __nv_bfloat16* Bbase_h = wt_hi + ((size_t)n * KM + tn * 128) * PC_DIM;
    const __nv_bfloat16* Bbase_l = wt_lo + ((size_t)n * KM + tn * 128) * PC_DIM;

    // fill one tile slot, NO commit (caller groups)
    auto fill_tile = [&](uint32_t dst, const __nv_bfloat16* src, int stride, int kc) {
        const __nv_bfloat16* s = src + kc * 64;
        #pragma unroll
        for (int i = 0; i < 4; i++) {
            const int idx = tid + 256 * i;
            const int r = idx >> 3, c = idx & 7;
            cp_async16(dst + (uint32_t)(r * PITCH * 2 + c * 16),
                       s + (size_t)r * stride + c * 8);
        }
    };
    auto stage_A = [&](int kc) {   // A_hi + A_lo of chunk kc, one commit group
        fill_tile(base + (uint32_t)(kc & 1) * TILE_BYTES, Abase_h, POSE_STRIDE, kc);
        fill_tile(base + (uint32_t)(2 + (kc & 1)) * TILE_BYTES, Abase_l, POSE_STRIDE, kc);
        cp_commit();
    };
    auto stage_BL = [&](int kc) { fill_tile(SLOT_BL, Bbase_l, PC_DIM, kc); cp_commit(); };
    auto stage_BH = [&](int kc) { fill_tile(SLOT_BH, Bbase_h, PC_DIM, kc); cp_commit(); };

    float acc[4][4][4];
    #pragma unroll
    for (int mi = 0; mi < 4; mi++)
        #pragma unroll
        for (int ni = 0; ni < 4; ni++)
            #pragma unroll
            for (int c = 0; c < 4; c++) acc[mi][ni][c] = 0.f;

    // prologue: kc=0 (groups: A0-pair, BH0, BL0)
    stage_A(0);
    stage_BH(0);
    stage_BL(0);

    #pragma unroll 1
    for (int kc = 0; kc < 4; ++kc) {
        const uint32_t A_hi = base + (uint32_t)(kc & 1) * TILE_BYTES;
        const uint32_t A_lo = base + (uint32_t)(2 + (kc & 1)) * TILE_BYTES;

        if (kc < 3) { stage_A(kc + 1); cp_wait1(); }
        else cp_wait0();
        __syncthreads();

        // ---- passAB: Ah shared between Bh and Bl per ks ----
        #pragma unroll
        for (int ks = 0; ks < 4; ks++) {
            unsigned af[4][4];
            #pragma unroll
            for (int mi = 0; mi < 4; mi++)
                ldmatrix_x4(af[mi][0], af[mi][1], af[mi][2], af[mi][3],
                            A_hi + 2u * (uint32_t)(a_off + mi * 16 * PITCH + ks * 16));
            unsigned bh[4][2], bl[4][2];
            #pragma unroll
            for (int p = 0; p < 2; p++) {
                ldmatrix_x4(bh[2*p][0], bh[2*p][1], bh[2*p+1][0], bh[2*p+1][1],
                            SLOT_BH + 2u * (uint32_t)(b_off + p * 16 * PITCH + ks * 16));
                ldmatrix_x4(bl[2*p][0], bl[2*p][1], bl[2*p+1][0], bl[2*p+1][1],
                            SLOT_BL + 2u * (uint32_t)(b_off + p * 16 * PITCH + ks * 16));
            }
            #pragma unroll
            for (int mi = 0; mi < 4; mi++)
                #pragma unroll
                for (int ni = 0; ni < 4; ni++) {
                    mma_bf16(acc[mi][ni][0], acc[mi][ni][1], acc[mi][ni][2], acc[mi][ni][3],
                             af[mi][0], af[mi][1], af[mi][2], af[mi][3],
                             bh[ni][0], bh[ni][1]);
                    mma_bf16(acc[mi][ni][0], acc[mi][ni][1], acc[mi][ni][2], acc[mi][ni][3],
                             af[mi][0], af[mi][1], af[mi][2], af[mi][3],
                             bl[ni][0], bl[ni][1]);
                }
        }
        __syncthreads();                 // BL fully read
        if (kc < 3) stage_BL(kc + 1);

        // ---- passAlBh ----
        #pragma unroll
        for (int ks = 0; ks < 4; ks++) {
            unsigned af[4][4];
            #pragma unroll
            for (int mi = 0; mi < 4; mi++)
                ldmatrix_x4(af[mi][0], af[mi][1], af[mi][2], af[mi][3],
                            A_lo + 2u * (uint32_t)(a_off + mi * 16 * PITCH + ks * 16));
            unsigned bh[4][2];
            #pragma unroll
            for (int p = 0; p < 2; p++)
                ldmatrix_x4(bh[2*p][0], bh[2*p][1], bh[2*p+1][0], bh[2*p+1][1],
                            SLOT_BH + 2u * (uint32_t)(b_off + p * 16 * PITCH + ks * 16));
            #pragma unroll
            for (int mi = 0; mi < 4; mi++)
                #pragma unroll
                for (int ni = 0; ni < 4; ni++)
                    mma_bf16(acc[mi][ni][0], acc[mi][ni][1], acc[mi][ni][2], acc[mi][ni][3],
                             af[mi][0], af[mi][1], af[mi][2], af[mi][3],
                             bh[ni][0], bh[ni][1]);
        }
        __syncthreads();                 // BH + A slots fully read
        if (kc < 3) stage_BH(kc + 1);
    }

    // epilogue (canonical D fragment layout)
    const int grp = lane >> 2, tig = lane & 3;
    #pragma unroll
    for (int mi = 0; mi < 4; mi++) {
        const int row = tm * 128 + wm * 64 + mi * 16 + grp;
        #pragma unroll
        for (int ni = 0; ni < 4; ni++) {
            const int col = tn * 128 + wn * 32 + ni * 8 + 2 * tig;
            float* p0 = g_votes + (size_t)row * VOTES_PER_B + n * KM + col;
            float* p1 = g_votes + (size_t)(row + 8) * VOTES_PER_B + n * KM + col;
            *(float2*)p0 = make_float2(acc[mi][ni][0], acc[mi][ni][1]);
            *(float2*)p1 = make_float2(acc[mi][ni][2], acc[mi][ni][3]);
        }
    }
}

// ---------------------------------------------------------------------------
// Kernel B (R11-exact): register-resident routing, direct GMEM loads.
// 148 CTAs x 800 threads (25 warps).
// ---------------------------------------------------------------------------
#define RT_GRID 148

__global__ __launch_bounds__(800, 1) void routing_kernel(
    const float* __restrict__ acts_prior,
    const float* __restrict__ ln_gamma,
    const float* __restrict__ ln_beta,
    const float* __restrict__ cls_weight,
    const float* __restrict__ cls_bias,
    float* __restrict__ out)
{
    __shared__ float sa[8];
    __shared__ float sagree[184];
    __shared__ float sra[184];

    const int tid  = threadIdx.x;
    const int wrp  = tid >> 5;
    const int lane = tid & 31;
    const int k    = wrp;

    const float4 g4  = *(const float4*)&ln_gamma[lane * 4];
    const float4 b4  = *(const float4*)&ln_beta[lane * 4];
    const float4 cw4 = *(const float4*)&cls_weight[k * MC_DIM + lane * 4];
    const float  bias = cls_bias[k];

    #pragma unroll 1
    for (int b = blockIdx.x; b < B_SZ; b += RT_GRID) {
        if (tid < N_IN) sa[tid] = acts_prior[(size_t)b * N_IN + tid];

        float4 v[N_IN];
        {
            const float* vb = g_votes + (size_t)b * VOTES_PER_B + k * MC_DIM + lane * 4;
            #pragma unroll
            for (int n = 0; n < N_IN; n++)
                v[n] = *(const float4*)(vb + n * KM);
        }
        __syncthreads();

        float ra[N_IN];
        #pragma unroll
        for (int n = 0; n < N_IN; n++) ra[n] = sa[n] * (1.f / 25.f);

        float4 pose;
        #pragma unroll 1
        for (int it = 0; it < 3; ++it) {
            if (it > 0) {
                #pragma unroll
                for (int n = 0; n < N_IN; n++) {
                    float d = v[n].x * pose.x + v[n].y * pose.y
                            + v[n].z * pose.z + v[n].w * pose.w;
                    d = warp_sum(d);
                    if (lane == 0) sagree[n * K_CAPS + k] = d * AGREE_SCALE;
                }
                __syncthreads();
                if (wrp < N_IN) {
                    const float x = (lane < K_CAPS) ? sagree[wrp * K_CAPS + lane] : -1e30f;
                    const float mx = warp_max(x);
                    const float e = (lane < K_CAPS) ? __expf(x - mx) : 0.f;
                    const float ssum = warp_sum(e);
                    if (lane < K_CAPS) {
                        const float r = e / ssum;
                        sra[wrp * K_CAPS + lane] = r * sa[wrp];
                        if (it == 2)
                            out[(size_t)B_SZ * K_CAPS + (size_t)b * 175
                                + wrp * K_CAPS + lane] = r;
                    }
                }
                __syncthreads();
                #pragma unroll
                for (int n = 0; n < N_IN; n++) ra[n] = sra[n * K_CAPS + k];
            }
            pose = make_float4(0.f, 0.f, 0.f, 0.f);
            #pragma unroll
            for (int n = 0; n < N_IN; n++) {
                pose.x = fmaf(ra[n], v[n].x, pose.x);
                pose.y = fmaf(ra[n], v[n].y, pose.y);
                pose.z = fmaf(ra[n], v[n].z, pose.z);
                pose.w = fmaf(ra[n], v[n].w, pose.w);
            }
            {
                float s = pose.x + pose.y + pose.z + pose.w;
                s = warp_sum(s);
                const float mu = s * (1.f / 128.f);
                float var = (pose.x - mu) * (pose.x - mu) + (pose.y - mu) * (pose.y - mu)
                          + (pose.z - mu) * (pose.z - mu) + (pose.w - mu) * (pose.w - mu);
                var = warp_sum(var) * (1.f / 128.f);
                const float rs = rsqrtf(var + LN_EPS);
                pose.x = (pose.x - mu) * rs * g4.x + b4.x;
                pose.y = (pose.y - mu) * rs * g4.y + b4.y;
                pose.z = (pose.z - mu) * rs * g4.z + b4.z;
                pose.w = (pose.w - mu) * rs * g4.w + b4.w;
            }
        }
        {
            float d = pose.x * cw4.x + pose.y * cw4.y + pose.z * cw4.z + pose.w * cw4.w;
            d = warp_sum(d);
            if (lane == 0) out[(size_t)b * K_CAPS + k] = d + bias;
        }
    }
}

// ---------------------------------------------------------------------------
extern "C" void kernel_launch(void* const* d_in, const int* in_sizes, int n_in,
                              void* d_out, int out_size)
{
    (void)in_sizes; (void)n_in; (void)out_size;
    const float* poses = (const float*)d_in[0];
    const float* acts  = (const float*)d_in[1];
    const float* w     = (const float*)d_in[2];
    const float* gamma = (const float*)d_in[3];
    const float* beta  = (const float*)d_in[4];
    const float* clsw  = (const float*)d_in[5];
    const float* clsb  = (const float*)d_in[6];
    float* out = (float*)d_out;

    __nv_bfloat16 *pa_hi, *pa_lo, *wt_hi, *wt_lo;
    cudaGetSymbolAddress((void**)&pa_hi, g_pa_hi);
    cudaGetSymbolAddress((void**)&pa_lo, g_pa_lo);
    cudaGetSymbolAddress((void**)&wt_hi, g_wt_hi);
    cudaGetSymbolAddress((void**)&wt_lo, g_wt_lo);

    decomp_fused_kernel<<<PO_BLKS + WT_BLKS, 256>>>(poses, w, pa_hi, pa_lo, wt_hi, wt_lo);

    cudaFuncSetAttribute(votes_hmma_kernel,
                         cudaFuncAttributeMaxDynamicSharedMemorySize,
                         VOTES_SMEM);
    votes_hmma_kernel<<<dim3(25, 32, 7), 256, VOTES_SMEM>>>(pa_hi, pa_lo, wt_hi, wt_lo);

    routing_kernel<<<RT_GRID, 800>>>(acts, gamma, beta, clsw, clsb, out);
}